// round 1
// baseline (speedup 1.0000x reference)
#include <cuda_runtime.h>
#include <math_constants.h>

// kNN graph, PyG knn_graph(loop=False) semantics, B=16 graphs x n=4096 pts, D=3, k=16.
// Output (float32, concatenated flat):
//   [0,        Nk)  : neighbor global indices (edge_index row 0)
//   [Nk,      2Nk)  : center  global indices (edge_index row 1)
//   [2Nk,     3Nk)  : top-k squared distances (ascending)
// with Nk = total_n * K, ordering (b*n+i)*K + m  (matches reference reshape(-1)).

#define K      16
#define NPER   4096
#define TPB    256
#define CPG    (NPER / TPB)   // CTAs per graph = 16

__global__ __launch_bounds__(TPB, 1)
void knn_topk_kernel(const float* __restrict__ pos,
                     float* __restrict__ out,
                     int total_n)
{
    extern __shared__ float smem[];
    float* sx = smem;
    float* sy = smem + NPER;
    float* sz = smem + 2 * NPER;
    float* ss = smem + 3 * NPER;

    const int graph = blockIdx.x / CPG;
    const int base  = graph * NPER;
    const float* gp = pos + (size_t)base * 3;

    // Stage this graph's points into SMEM (SoA) + precompute squared norms.
    for (int p = threadIdx.x; p < NPER; p += TPB) {
        float x = gp[3 * p + 0];
        float y = gp[3 * p + 1];
        float z = gp[3 * p + 2];
        sx[p] = x; sy[p] = y; sz[p] = z;
        ss[p] = x * x + y * y + z * z;
    }
    __syncthreads();

    const int   q  = (blockIdx.x % CPG) * TPB + threadIdx.x;   // local query idx
    const float qx = sx[q], qy = sy[q], qz = sz[q], qs = ss[q];

    // Register-resident sorted top-K (ascending distance).
    float bd[K];
    int   bi[K];
#pragma unroll
    for (int m = 0; m < K; ++m) { bd[m] = CUDART_INF_F; bi[m] = 0; }
    float worst = CUDART_INF_F;

#pragma unroll 2
    for (int j0 = 0; j0 < NPER; j0 += 4) {
        const float4 x4 = *reinterpret_cast<const float4*>(sx + j0);
        const float4 y4 = *reinterpret_cast<const float4*>(sy + j0);
        const float4 z4 = *reinterpret_cast<const float4*>(sz + j0);
        const float4 s4 = *reinterpret_cast<const float4*>(ss + j0);

        // Same formula as reference: sq_i + sq_j - 2*dot  (keeps near-tie ordering aligned)
        float d0 = fmaf(-2.f, fmaf(qz, z4.x, fmaf(qy, y4.x, qx * x4.x)), qs + s4.x);
        float d1 = fmaf(-2.f, fmaf(qz, z4.y, fmaf(qy, y4.y, qx * x4.y)), qs + s4.y);
        float d2 = fmaf(-2.f, fmaf(qz, z4.z, fmaf(qy, y4.z, qx * x4.z)), qs + s4.z);
        float d3 = fmaf(-2.f, fmaf(qz, z4.w, fmaf(qy, y4.w, qx * x4.w)), qs + s4.w);

        const float mn = fminf(fminf(d0, d1), fminf(d2, d3));
        if (mn < worst) {
#pragma unroll
            for (int t = 0; t < 4; ++t) {
                const float dd = (t == 0) ? d0 : (t == 1) ? d1 : (t == 2) ? d2 : d3;
                const int   j  = j0 + t;
                // strict '<' : equal distances keep the earlier (lower) index,
                // matching jax.lax.top_k tie-breaking. j==q (self, d~0) excluded.
                if (dd < worst && j != q) {
                    float dc = dd; int ic = j;
#pragma unroll
                    for (int m = 0; m < K; ++m) {
                        const bool  sw = dc < bd[m];
                        const float fo = sw ? bd[m] : dc;
                        const int   io = sw ? bi[m] : ic;
                        bd[m] = sw ? dc : bd[m];
                        bi[m] = sw ? ic : bi[m];
                        dc = fo; ic = io;
                    }
                    worst = bd[K - 1];
                }
            }
        }
    }

    // Emit: neighbors (global), centers, distances — all as float32.
    const int    gq = base + q;
    const size_t Nk = (size_t)total_n * K;
#pragma unroll
    for (int m = 0; m < K; ++m) {
        const size_t e = (size_t)gq * K + m;
        out[e]          = (float)(bi[m] + base);
        out[Nk + e]     = (float)gq;
        out[2 * Nk + e] = bd[m];
    }
}

extern "C" void kernel_launch(void* const* d_in, const int* in_sizes, int n_in,
                              void* d_out, int out_size)
{
    const float* pos = (const float*)d_in[0];
    // d_in[1] = batch_idx (contiguous equal-size graphs, PyG convention) — implied by layout.
    // d_in[2] = k (device scalar) — fixed at 16 for this problem.
    const int total_n = in_sizes[0] / 3;
    const int ngraphs = total_n / NPER;

    const int smem_bytes = 4 * NPER * (int)sizeof(float);   // 64 KB
    cudaFuncSetAttribute(knn_topk_kernel,
                         cudaFuncAttributeMaxDynamicSharedMemorySize, smem_bytes);

    knn_topk_kernel<<<ngraphs * CPG, TPB, smem_bytes>>>(pos, (float*)d_out, total_n);
}

// round 2
// speedup vs baseline: 2.0247x; 2.0247x over previous
#include <cuda_runtime.h>
#include <math_constants.h>

// kNN graph, PyG knn_graph(loop=False): B=16 graphs x n=4096 pts, D=3, k=16.
// Output (float32 flat): [nbr_global | centers | topk_d2], each total_n*K,
// ordering (b*n+i)*K + m (matches reference reshape(-1)).

#define K        16
#define NPER     4096
#define TPB      256
#define CPG      (NPER / TPB)   // 16 CTAs per graph
#define PB       8              // pending-buffer slots per thread
#define FLUSH_AT 5              // flush when cnt >= 5 (room for 4 more pushes)

#define FMA_F32X2(out, a, b, c) \
    asm("fma.rn.f32x2 %0, %1, %2, %3;" : "=l"(out) : "l"(a), "l"(b), "l"(c))
#define MUL_F32X2_(out, a, b) \
    asm("mul.rn.f32x2 %0, %1, %2;" : "=l"(out) : "l"(a), "l"(b))
#define ADD_F32X2_(out, a, b) \
    asm("add.rn.f32x2 %0, %1, %2;" : "=l"(out) : "l"(a), "l"(b))
#define PACK2(out, lo, hi) \
    asm("mov.b64 %0, {%1, %2};" : "=l"(out) : "r"(lo), "r"(hi))
#define UNPACK2(lo, hi, in) \
    asm("mov.b64 {%0, %1}, %2;" : "=r"(lo), "=r"(hi) : "l"(in))

__global__ __launch_bounds__(TPB, 1)
void knn_topk_kernel(const float* __restrict__ pos,
                     float* __restrict__ out,
                     int total_n)
{
    extern __shared__ float smem[];
    float* sx = smem;
    float* sy = smem +     NPER;
    float* sz = smem + 2 * NPER;
    float* ss = smem + 3 * NPER;
    float* pdm = smem + 4 * NPER;               // [PB][TPB] pending distances
    int*   pim = (int*)(smem + 4 * NPER + PB * TPB);  // [PB][TPB] pending indices

    const int graph = blockIdx.x / CPG;
    const int base  = graph * NPER;
    const float* gp = pos + (size_t)base * 3;

    // Stage graph points (SoA) + squared norms into SMEM.
    for (int p = threadIdx.x; p < NPER; p += TPB) {
        float x = gp[3 * p + 0];
        float y = gp[3 * p + 1];
        float z = gp[3 * p + 2];
        sx[p] = x; sy[p] = y; sz[p] = z;
        ss[p] = x * x + y * y + z * z;
    }
    __syncthreads();

    const int   tid = threadIdx.x;
    const int   q   = (blockIdx.x % CPG) * TPB + tid;   // local query idx
    const float qx = sx[q], qy = sy[q], qz = sz[q], qs = ss[q];

    // Packed query broadcasts for f32x2 math.
    unsigned long long qx2, qy2, qz2, qs2, m2;
    {
        const unsigned xb = __float_as_uint(qx), yb = __float_as_uint(qy);
        const unsigned zb = __float_as_uint(qz), sb = __float_as_uint(qs);
        const unsigned nb = __float_as_uint(-2.0f);
        PACK2(qx2, xb, xb); PACK2(qy2, yb, yb); PACK2(qz2, zb, zb);
        PACK2(qs2, sb, sb); PACK2(m2, nb, nb);
    }

    // Register-resident sorted top-K (ascending).
    float bd[K];
    int   bi[K];
#pragma unroll
    for (int m = 0; m < K; ++m) { bd[m] = CUDART_INF_F; bi[m] = 0; }
    float worst = CUDART_INF_F;
    int   cnt = 0;

#pragma unroll 2
    for (int j0 = 0; j0 < NPER; j0 += 4) {
        const ulonglong2 X = *reinterpret_cast<const ulonglong2*>(sx + j0);
        const ulonglong2 Y = *reinterpret_cast<const ulonglong2*>(sy + j0);
        const ulonglong2 Z = *reinterpret_cast<const ulonglong2*>(sz + j0);
        const ulonglong2 S = *reinterpret_cast<const ulonglong2*>(ss + j0);

        // d = (qs + s) - 2*(qx*x + qy*y + qz*z), identical op order/rounding
        // to the scalar reference formula (f32x2 = two independent fp32 FMAs).
        unsigned long long dot0, dot1, t0, t1, dp0, dp1;
        MUL_F32X2_(dot0, qx2, X.x);
        FMA_F32X2(dot0, qy2, Y.x, dot0);
        FMA_F32X2(dot0, qz2, Z.x, dot0);
        ADD_F32X2_(t0, S.x, qs2);
        FMA_F32X2(dp0, m2, dot0, t0);

        MUL_F32X2_(dot1, qx2, X.y);
        FMA_F32X2(dot1, qy2, Y.y, dot1);
        FMA_F32X2(dot1, qz2, Z.y, dot1);
        ADD_F32X2_(t1, S.y, qs2);
        FMA_F32X2(dp1, m2, dot1, t1);

        unsigned u0, u1, u2, u3;
        UNPACK2(u0, u1, dp0);
        UNPACK2(u2, u3, dp1);
        const float d0 = __uint_as_float(u0), d1 = __uint_as_float(u1);
        const float d2 = __uint_as_float(u2), d3 = __uint_as_float(u3);

        const float mn = fminf(fminf(d0, d1), fminf(d2, d3));
        if (mn < worst) {
            // Push passing candidates to the per-thread SMEM FIFO (cheap).
            if (d0 < worst && (j0 + 0) != q) { pdm[cnt * TPB + tid] = d0; pim[cnt * TPB + tid] = j0 + 0; ++cnt; }
            if (d1 < worst && (j0 + 1) != q) { pdm[cnt * TPB + tid] = d1; pim[cnt * TPB + tid] = j0 + 1; ++cnt; }
            if (d2 < worst && (j0 + 2) != q) { pdm[cnt * TPB + tid] = d2; pim[cnt * TPB + tid] = j0 + 2; ++cnt; }
            if (d3 < worst && (j0 + 3) != q) { pdm[cnt * TPB + tid] = d3; pim[cnt * TPB + tid] = j0 + 3; ++cnt; }
        }

        // Warp-synchronized flush: all lanes drain together (amortizes the
        // expensive sorted-insert chain across the warp).
        if (__any_sync(0xFFFFFFFFu, cnt >= FLUSH_AT)) {
            for (int p = 0; p < cnt; ++p) {
                float dc = pdm[p * TPB + tid];
                int   ic = pim[p * TPB + tid];
                if (dc < worst) {
#pragma unroll
                    for (int m = 0; m < K; ++m) {
                        const bool  sw = dc < bd[m];   // strict '<': ties keep lower index
                        const float fo = sw ? bd[m] : dc;
                        const int   io = sw ? bi[m] : ic;
                        bd[m] = sw ? dc : bd[m];
                        bi[m] = sw ? ic : bi[m];
                        dc = fo; ic = io;
                    }
                    worst = bd[K - 1];
                }
            }
            cnt = 0;
        }
    }

    // Final drain of residual pending candidates.
    for (int p = 0; p < cnt; ++p) {
        float dc = pdm[p * TPB + tid];
        int   ic = pim[p * TPB + tid];
        if (dc < worst) {
#pragma unroll
            for (int m = 0; m < K; ++m) {
                const bool  sw = dc < bd[m];
                const float fo = sw ? bd[m] : dc;
                const int   io = sw ? bi[m] : ic;
                bd[m] = sw ? dc : bd[m];
                bi[m] = sw ? ic : bi[m];
                dc = fo; ic = io;
            }
            worst = bd[K - 1];
        }
    }

    // Emit: neighbors (global), centers, distances — all float32.
    const int    gq = base + q;
    const size_t Nk = (size_t)total_n * K;
#pragma unroll
    for (int m = 0; m < K; ++m) {
        const size_t e = (size_t)gq * K + m;
        out[e]          = (float)(bi[m] + base);
        out[Nk + e]     = (float)gq;
        out[2 * Nk + e] = bd[m];
    }
}

extern "C" void kernel_launch(void* const* d_in, const int* in_sizes, int n_in,
                              void* d_out, int out_size)
{
    const float* pos = (const float*)d_in[0];
    const int total_n = in_sizes[0] / 3;
    const int ngraphs = total_n / NPER;

    const int smem_bytes = (4 * NPER + 2 * PB * TPB) * (int)sizeof(float); // 80 KB
    cudaFuncSetAttribute(knn_topk_kernel,
                         cudaFuncAttributeMaxDynamicSharedMemorySize, smem_bytes);

    knn_topk_kernel<<<ngraphs * CPG, TPB, smem_bytes>>>(pos, (float*)d_out, total_n);
}

// round 3
// speedup vs baseline: 2.1033x; 1.0388x over previous
#include <cuda_runtime.h>
#include <math_constants.h>

// kNN graph, PyG knn_graph(loop=False): B=16 graphs x n=4096 pts, D=3, k=16.
// Output (float32 flat): [nbr_global | centers | topk_d2], each total_n*K,
// ordering (b*n+i)*K + m (matches reference reshape(-1)).

#define K        16
#define NPER     4096
#define TPB      256
#define CPG      (NPER / TPB)   // 16 CTAs per graph
#define PB       12             // pending-buffer slots per thread
#define FLUSH_AT 5              // flush when cnt >= 5 (room for 8 more pushes)

#define FMA_F32X2(out, a, b, c) \
    asm("fma.rn.f32x2 %0, %1, %2, %3;" : "=l"(out) : "l"(a), "l"(b), "l"(c))
#define MUL_F32X2_(out, a, b) \
    asm("mul.rn.f32x2 %0, %1, %2;" : "=l"(out) : "l"(a), "l"(b))
#define ADD_F32X2_(out, a, b) \
    asm("add.rn.f32x2 %0, %1, %2;" : "=l"(out) : "l"(a), "l"(b))
#define PACK2(out, lo, hi) \
    asm("mov.b64 %0, {%1, %2};" : "=l"(out) : "r"(lo), "r"(hi))
#define UNPACK2(lo, hi, in) \
    asm("mov.b64 {%0, %1}, %2;" : "=r"(lo), "=r"(hi) : "l"(in))

__device__ __forceinline__ void sorted_insert(float dc, int ic,
                                              float (&bd)[K], int (&bi)[K],
                                              float& worst)
{
#pragma unroll
    for (int m = 0; m < K; ++m) {
        const bool  sw = dc < bd[m];   // strict '<': ties keep lower index
        const float fo = sw ? bd[m] : dc;
        const int   io = sw ? bi[m] : ic;
        bd[m] = sw ? dc : bd[m];
        bi[m] = sw ? ic : bi[m];
        dc = fo; ic = io;
    }
    worst = bd[K - 1];
}

__global__ __launch_bounds__(TPB, 2)
void knn_topk_kernel(const float* __restrict__ pos,
                     float* __restrict__ out,
                     int total_n)
{
    extern __shared__ float smem[];
    float* sx = smem;
    float* sy = smem +     NPER;
    float* sz = smem + 2 * NPER;
    float* ss = smem + 3 * NPER;
    float* pdm = smem + 4 * NPER;                     // [PB][TPB] pending dists
    int*   pim = (int*)(smem + 4 * NPER + PB * TPB);  // [PB][TPB] pending idx

    const int graph = blockIdx.x / CPG;
    const int base  = graph * NPER;
    const float* gp = pos + (size_t)base * 3;

    // Stage graph points (SoA) + squared norms into SMEM.
    for (int p = threadIdx.x; p < NPER; p += TPB) {
        float x = gp[3 * p + 0];
        float y = gp[3 * p + 1];
        float z = gp[3 * p + 2];
        sx[p] = x; sy[p] = y; sz[p] = z;
        ss[p] = x * x + y * y + z * z;
    }
    __syncthreads();

    const int   tid = threadIdx.x;
    const int   q   = (blockIdx.x % CPG) * TPB + tid;   // local query idx
    const float qx = sx[q], qy = sy[q], qz = sz[q], qs = ss[q];

    // Packed query broadcasts for f32x2 math.
    unsigned long long qx2, qy2, qz2, qs2, m2;
    {
        const unsigned xb = __float_as_uint(qx), yb = __float_as_uint(qy);
        const unsigned zb = __float_as_uint(qz), sb = __float_as_uint(qs);
        const unsigned nb = __float_as_uint(-2.0f);
        PACK2(qx2, xb, xb); PACK2(qy2, yb, yb); PACK2(qz2, zb, zb);
        PACK2(qs2, sb, sb); PACK2(m2, nb, nb);
    }

    // Register-resident sorted top-K (ascending).
    float bd[K];
    int   bi[K];
#pragma unroll
    for (int m = 0; m < K; ++m) { bd[m] = CUDART_INF_F; bi[m] = 0; }
    float worst = CUDART_INF_F;
    int   cnt = 0;

#pragma unroll 2
    for (int j0 = 0; j0 < NPER; j0 += 8) {
        const ulonglong2 Xa = *reinterpret_cast<const ulonglong2*>(sx + j0);
        const ulonglong2 Ya = *reinterpret_cast<const ulonglong2*>(sy + j0);
        const ulonglong2 Za = *reinterpret_cast<const ulonglong2*>(sz + j0);
        const ulonglong2 Sa = *reinterpret_cast<const ulonglong2*>(ss + j0);
        const ulonglong2 Xb = *reinterpret_cast<const ulonglong2*>(sx + j0 + 4);
        const ulonglong2 Yb = *reinterpret_cast<const ulonglong2*>(sy + j0 + 4);
        const ulonglong2 Zb = *reinterpret_cast<const ulonglong2*>(sz + j0 + 4);
        const ulonglong2 Sb = *reinterpret_cast<const ulonglong2*>(ss + j0 + 4);

        // d = (qs + s) - 2*(qx*x + qy*y + qz*z); f32x2 = two independent fp32
        // FMAs, identical op order/rounding to the scalar reference formula.
        unsigned long long dt, tt, dp0, dp1, dp2, dp3;
        MUL_F32X2_(dt, qx2, Xa.x); FMA_F32X2(dt, qy2, Ya.x, dt); FMA_F32X2(dt, qz2, Za.x, dt);
        ADD_F32X2_(tt, Sa.x, qs2); FMA_F32X2(dp0, m2, dt, tt);
        MUL_F32X2_(dt, qx2, Xa.y); FMA_F32X2(dt, qy2, Ya.y, dt); FMA_F32X2(dt, qz2, Za.y, dt);
        ADD_F32X2_(tt, Sa.y, qs2); FMA_F32X2(dp1, m2, dt, tt);
        MUL_F32X2_(dt, qx2, Xb.x); FMA_F32X2(dt, qy2, Yb.x, dt); FMA_F32X2(dt, qz2, Zb.x, dt);
        ADD_F32X2_(tt, Sb.x, qs2); FMA_F32X2(dp2, m2, dt, tt);
        MUL_F32X2_(dt, qx2, Xb.y); FMA_F32X2(dt, qy2, Yb.y, dt); FMA_F32X2(dt, qz2, Zb.y, dt);
        ADD_F32X2_(tt, Sb.y, qs2); FMA_F32X2(dp3, m2, dt, tt);

        unsigned u0, u1, u2, u3, u4, u5, u6, u7;
        UNPACK2(u0, u1, dp0); UNPACK2(u2, u3, dp1);
        UNPACK2(u4, u5, dp2); UNPACK2(u6, u7, dp3);
        const float d0 = __uint_as_float(u0), d1 = __uint_as_float(u1);
        const float d2 = __uint_as_float(u2), d3 = __uint_as_float(u3);
        const float d4 = __uint_as_float(u4), d5 = __uint_as_float(u5);
        const float d6 = __uint_as_float(u6), d7 = __uint_as_float(u7);

        const float mn = fminf(fminf(fminf(d0, d1), fminf(d2, d3)),
                               fminf(fminf(d4, d5), fminf(d6, d7)));
        if (mn < worst) {
            if (d0 < worst && (j0 + 0) != q) { pdm[cnt * TPB + tid] = d0; pim[cnt * TPB + tid] = j0 + 0; ++cnt; }
            if (d1 < worst && (j0 + 1) != q) { pdm[cnt * TPB + tid] = d1; pim[cnt * TPB + tid] = j0 + 1; ++cnt; }
            if (d2 < worst && (j0 + 2) != q) { pdm[cnt * TPB + tid] = d2; pim[cnt * TPB + tid] = j0 + 2; ++cnt; }
            if (d3 < worst && (j0 + 3) != q) { pdm[cnt * TPB + tid] = d3; pim[cnt * TPB + tid] = j0 + 3; ++cnt; }
            if (d4 < worst && (j0 + 4) != q) { pdm[cnt * TPB + tid] = d4; pim[cnt * TPB + tid] = j0 + 4; ++cnt; }
            if (d5 < worst && (j0 + 5) != q) { pdm[cnt * TPB + tid] = d5; pim[cnt * TPB + tid] = j0 + 5; ++cnt; }
            if (d6 < worst && (j0 + 6) != q) { pdm[cnt * TPB + tid] = d6; pim[cnt * TPB + tid] = j0 + 6; ++cnt; }
            if (d7 < worst && (j0 + 7) != q) { pdm[cnt * TPB + tid] = d7; pim[cnt * TPB + tid] = j0 + 7; ++cnt; }
        }

        // Warp-synchronized flush: all lanes drain together.
        if (__any_sync(0xFFFFFFFFu, cnt >= FLUSH_AT)) {
            for (int p = 0; p < cnt; ++p) {
                const float dc = pdm[p * TPB + tid];
                const int   ic = pim[p * TPB + tid];
                if (dc < worst) sorted_insert(dc, ic, bd, bi, worst);
            }
            cnt = 0;
        }
    }

    // Final drain.
    for (int p = 0; p < cnt; ++p) {
        const float dc = pdm[p * TPB + tid];
        const int   ic = pim[p * TPB + tid];
        if (dc < worst) sorted_insert(dc, ic, bd, bi, worst);
    }

    // Emit: neighbors (global), centers, distances — all float32.
    const int    gq = base + q;
    const size_t Nk = (size_t)total_n * K;
#pragma unroll
    for (int m = 0; m < K; ++m) {
        const size_t e = (size_t)gq * K + m;
        out[e]          = (float)(bi[m] + base);
        out[Nk + e]     = (float)gq;
        out[2 * Nk + e] = bd[m];
    }
}

extern "C" void kernel_launch(void* const* d_in, const int* in_sizes, int n_in,
                              void* d_out, int out_size)
{
    const float* pos = (const float*)d_in[0];
    const int total_n = in_sizes[0] / 3;
    const int ngraphs = total_n / NPER;

    const int smem_bytes = (4 * NPER + 2 * PB * TPB) * (int)sizeof(float); // 88 KB
    cudaFuncSetAttribute(knn_topk_kernel,
                         cudaFuncAttributeMaxDynamicSharedMemorySize, smem_bytes);

    knn_topk_kernel<<<ngraphs * CPG, TPB, smem_bytes>>>(pos, (float*)d_out, total_n);
}